// round 7
// baseline (speedup 1.0000x reference)
#include <cuda_runtime.h>
#include <cuda_bf16.h>
#include <cstdint>

// Problem dims
#define QN 2048
#define SN 8
#define DN 2048
#define SPN 100
#define NCLS 20
#define MROWS (QN * SN)          // 16384
#define NCOLS (SPN * SN)         // 800
#define NPAD 896                 // 7 * 128
#define LBDA 0.1f
#define ILBDA 10.0f
#define FP8SCALE 16.0f
#define INV256 0.00390625f

// GEMM tiling: CTA 256x128 x K128(fp8), SW128-swizzled smem, 3-stage cp.async
#define BM 256
#define BN 128
#define BK 128                   // fp8 elems = 128 B rows
#define NST 3
#define A_STG_B (BM * 128)       // 32768
#define B_STG_B (BN * 128)       // 16384
#define STG_B (A_STG_B + B_STG_B)
#define EPI_PITCH 132            // fp32 elems per epilogue smem row
#define SM_BYTES (NST * STG_B)   // 147456 (>= 256*132*4 = 135168)

// -------- scratch (device globals; allocation-free kernel_launch) --------
__device__ uint8_t g_A[(size_t)MROWS * DN];   // 32 MB (e4m3)
__device__ uint8_t g_B[(size_t)NPAD * DN];    // 1.8 MB (e4m3)
__device__ float g_tfn[MROWS];
__device__ float g_sfn[NPAD];
__device__ float g_invcnt[NCLS];

// -------- PTX helpers (compute_103-safe) --------
__device__ __forceinline__ void cpa16(uint32_t saddr, const void* g) {
    asm volatile("cp.async.cg.shared.global [%0], [%1], 16;"
                 :: "r"(saddr), "l"(__cvta_generic_to_global(g)) : "memory");
}
__device__ __forceinline__ void cpa_commit() {
    asm volatile("cp.async.commit_group;" ::: "memory");
}
__device__ __forceinline__ void cpa_wait1() {
    asm volatile("cp.async.wait_group 1;" ::: "memory");
}
__device__ __forceinline__ uint32_t smem_u32(const void* p) {
    uint32_t a;
    asm("{ .reg .u64 t; cvta.to.shared.u64 t, %1; cvt.u32.u64 %0, t; }"
        : "=r"(a) : "l"(p));
    return a;
}
#define LDSM4(r0, r1, r2, r3, addr)                                         \
    asm volatile("ldmatrix.sync.aligned.m8n8.x4.shared.b16 {%0,%1,%2,%3}, [%4];" \
                 : "=r"(r0), "=r"(r1), "=r"(r2), "=r"(r3) : "r"(addr))

__device__ __forceinline__ void mma_fp8(float* d, const uint32_t* a,
                                        uint32_t b0, uint32_t b1) {
    asm volatile(
        "mma.sync.aligned.m16n8k32.row.col.f32.e4m3.e4m3.f32 "
        "{%0,%1,%2,%3}, {%4,%5,%6,%7}, {%8,%9}, {%0,%1,%2,%3};"
        : "+f"(d[0]), "+f"(d[1]), "+f"(d[2]), "+f"(d[3])
        : "r"(a[0]), "r"(a[1]), "r"(a[2]), "r"(a[3]), "r"(b0), "r"(b1));
}
// pack two floats -> two e4m3 bytes: low byte = e0, high byte = e1
__device__ __forceinline__ uint16_t f2e4m3x2(float e0, float e1) {
    uint16_t r;
    asm("cvt.rn.satfinite.e4m3x2.f32 %0, %1, %2;" : "=h"(r) : "f"(e1), "f"(e0));
    return r;
}

// -------- kernel 0: zero output + class inverse counts --------
__global__ void k_zero(float* __restrict__ out, int n,
                       const int* __restrict__ labels) {
    int i = blockIdx.x * blockDim.x + threadIdx.x;
    if (i < n) out[i] = 0.0f;
    if (blockIdx.x == 0) {
        __shared__ int cnt[NCLS];
        if (threadIdx.x < NCLS) cnt[threadIdx.x] = 0;
        __syncthreads();
        if (threadIdx.x < SPN) atomicAdd(&cnt[labels[threadIdx.x]], 1);
        __syncthreads();
        if (threadIdx.x < NCLS) {
            int c = cnt[threadIdx.x];
            g_invcnt[threadIdx.x] = 1.0f / (float)(c > 0 ? c : 1);
        }
    }
}

// -------- kernel 1: fp32 -> e4m3 (x16) + fp32 row norms. 4 rows/block ----
__global__ void __launch_bounds__(256) k_conv(const float* __restrict__ tf,
                                              const float* __restrict__ sf) {
    const int rg = threadIdx.x >> 6;      // 0..3
    const int t = threadIdx.x & 63;       // 64 threads per row
    int row = blockIdx.x * 4 + rg;

    const float* src;
    uint8_t* dst;
    float* norms;
    bool pad = false;
    if (row < MROWS) {
        src = tf + (size_t)row * DN;
        dst = g_A + (size_t)row * DN;
        norms = &g_tfn[row];
    } else {
        int r = row - MROWS;
        pad = (r >= NCOLS);
        src = sf + (size_t)r * DN;
        dst = g_B + (size_t)r * DN;
        norms = &g_sfn[r];
    }

    float ss = 0.0f;
    uint2 ov[8];
    #pragma unroll
    for (int j = 0; j < 8; j++) ov[j] = make_uint2(0u, 0u);
    if (!pad) {
        const float4* s = reinterpret_cast<const float4*>(src);
        float4 v[8];
        #pragma unroll
        for (int j = 0; j < 8; j++) v[j] = s[t + 64 * j];
        #pragma unroll
        for (int j = 0; j < 8; j++) {
            ss = fmaf(v[j].x, v[j].x, fmaf(v[j].y, v[j].y,
                 fmaf(v[j].z, v[j].z, fmaf(v[j].w, v[j].w, ss))));
            uint16_t lo = f2e4m3x2(v[j].x * FP8SCALE, v[j].y * FP8SCALE);
            uint16_t hi = f2e4m3x2(v[j].z * FP8SCALE, v[j].w * FP8SCALE);
            ov[j].x = (uint32_t)lo | ((uint32_t)hi << 16);
        }
    }
    // pack pairs: each uint2 slot holds 8 bytes = 8 fp8 (we used .x only: 4)
    // store as 8B per j covering 8 elems? No: 16 floats/thread/row-chunk.
    // Each j handles 4 floats -> 4 bytes; combine j pairs into uint2 of 8 bytes.
    uint2* drow = reinterpret_cast<uint2*>(dst);
    #pragma unroll
    for (int j = 0; j < 4; j++) {
        uint2 w = make_uint2(ov[2 * j].x, ov[2 * j + 1].x);
        drow[t * 4 + j] = w;   // 8 bytes = floats [t*32 + j*8 .. +7]
    }

    #pragma unroll
    for (int o = 16; o; o >>= 1) ss += __shfl_xor_sync(0xFFFFFFFFu, ss, o);
    __shared__ float ws[8];
    if ((threadIdx.x & 31) == 0) ws[threadIdx.x >> 5] = ss;
    __syncthreads();
    if (t == 0 && !pad)
        *norms = sqrtf(ws[rg * 2] + ws[rg * 2 + 1]);
}

// -------- OTAM soft-DTW --------
__device__ __forceinline__ float softmin2(float a, float b) {
    float mn = fminf(a, b);
    float df = fabsf(a - b);
    return mn - LBDA * __logf(1.0f + __expf(-df * ILBDA));
}
__device__ __forceinline__ float softmin3(float a, float b, float c) {
    float mn = fminf(a, fminf(b, c));
    float s = __expf((mn - a) * ILBDA) + __expf((mn - b) * ILBDA) + __expf((mn - c) * ILBDA);
    return mn - LBDA * __logf(s);
}

template <bool TR>
__device__ __forceinline__ float otam_dp(const float d[8][8]) {
    float prev[10];
    prev[0] = 0.0f;
    #pragma unroll
    for (int m = 1; m <= 8; m++) {
        float v = TR ? d[m - 1][0] : d[0][m - 1];
        prev[m] = prev[m - 1] + v;
    }
    prev[9] = prev[8];
    #pragma unroll
    for (int i = 1; i < 8; i++) {
        float cur[10];
        cur[0] = 0.0f;
        {
            float v = TR ? d[0][i] : d[i][0];
            cur[1] = v + softmin3(prev[0], prev[1], 0.0f);
        }
        #pragma unroll
        for (int m = 2; m <= 8; m++) {
            float v = TR ? d[m - 1][i] : d[i][m - 1];
            cur[m] = v + softmin2(prev[m - 1], cur[m - 1]);
        }
        cur[9] = softmin3(prev[8], prev[9], cur[8]);
        #pragma unroll
        for (int m = 0; m < 10; m++) prev[m] = cur[m];
    }
    return prev[9];
}

// -------- kernel 2: fp8 GEMM + fused OTAM epilogue --------
__global__ void __launch_bounds__(256, 1) k_gemm(const int* __restrict__ labels,
                                                 float* __restrict__ out) {
    extern __shared__ __align__(128) char smem_raw[];
    uint32_t sb = smem_u32(smem_raw);

    const int tid = threadIdx.x;
    const int lane = tid & 31;
    const int warp = tid >> 5;
    const int wm = warp >> 1;     // 0..3
    const int wn = warp & 1;      // 0..1
    const int bm = blockIdx.y * BM;
    const int bn = blockIdx.x * BN;

    // loader: 16B chunks; thread -> (row tid>>3, chunk tid&7), rows += 32
    const int lrow = tid >> 3;
    const int lcc = tid & 7;
    const uint32_t s_off =
        (uint32_t)(lrow * 128 + ((lcc ^ (lrow & 7)) << 4));
    const uint8_t* gA = g_A + (size_t)(bm + lrow) * DN + lcc * 16;
    const uint8_t* gB = g_B + (size_t)(bn + lrow) * DN + lcc * 16;

    float acc[4][8][4];
    #pragma unroll
    for (int i = 0; i < 4; i++)
        #pragma unroll
        for (int j = 0; j < 8; j++)
            #pragma unroll
            for (int k = 0; k < 4; k++) acc[i][j][k] = 0.0f;

    const int NSTG = DN / BK;  // 16

    auto load_stage = [&](int st, int k0) {
        uint32_t base = sb + (uint32_t)(st * STG_B);
        #pragma unroll
        for (int i = 0; i < 8; i++)
            cpa16(base + s_off + (uint32_t)(i * 32 * 128),
                  gA + k0 + (size_t)i * 32 * DN);
        #pragma unroll
        for (int i = 0; i < 4; i++)
            cpa16(base + A_STG_B + s_off + (uint32_t)(i * 32 * 128),
                  gB + k0 + (size_t)i * 32 * DN);
        cpa_commit();
    };

    load_stage(0, 0);
    load_stage(1, BK);

    const uint32_t hl = (uint32_t)(lane >> 4);
    const uint32_t l7 = (uint32_t)(lane & 7);
    const uint32_t aRow = (uint32_t)((wm * 64 + (lane & 15)) * 128);
    const uint32_t bRow = (uint32_t)(A_STG_B + (wn * 64 + (lane & 15)) * 128);

    #pragma unroll 1
    for (int s = 0; s < NSTG; s++) {
        cpa_wait1();
        __syncthreads();
        if (s + 2 < NSTG) load_stage((s + 2) % NST, (s + 2) * BK);
        else cpa_commit();

        uint32_t stb = sb + (uint32_t)((s % NST) * STG_B);

        #pragma unroll
        for (int kk = 0; kk < 4; kk++) {
            uint32_t xc = (((uint32_t)(2 * kk) + hl) ^ l7) << 4;
            uint32_t a[4][4];
            #pragma unroll
            for (int i = 0; i < 4; i++)
                LDSM4(a[i][0], a[i][1], a[i][2], a[i][3],
                      stb + aRow + (uint32_t)(i * 16 * 128) + xc);
            uint32_t b[4][4];
            #pragma unroll
            for (int j = 0; j < 4; j++)
                LDSM4(b[j][0], b[j][1], b[j][2], b[j][3],
                      stb + bRow + (uint32_t)(j * 16 * 128) + xc);
            #pragma unroll
            for (int i = 0; i < 4; i++)
                #pragma unroll
                for (int j = 0; j < 4; j++) {
                    mma_fp8(acc[i][2 * j],     a[i], b[j][0], b[j][2]);
                    mma_fp8(acc[i][2 * j + 1], a[i], b[j][1], b[j][3]);
                }
        }
    }

    // ---- fused epilogue: acc -> smem tile, then per-pair OTAM DP ----
    __syncthreads();   // all warps done reading stage buffers
    float* ds = reinterpret_cast<float*>(smem_raw);
    {
        const int r0l = wm * 64 + (lane >> 2);
        const int c0l = wn * 64 + (lane & 3) * 2;
        #pragma unroll
        for (int i = 0; i < 4; i++) {
            #pragma unroll
            for (int j = 0; j < 8; j++) {
                int r = r0l + i * 16;
                int c = c0l + j * 8;
                *reinterpret_cast<float2*>(&ds[r * EPI_PITCH + c]) =
                    make_float2(acc[i][j][0], acc[i][j][1]);
                *reinterpret_cast<float2*>(&ds[(r + 8) * EPI_PITCH + c]) =
                    make_float2(acc[i][j][2], acc[i][j][3]);
            }
        }
    }
    __syncthreads();

    const int qb = bm >> 3;    // base q of this tile
    const int spb = bn >> 3;   // base sp of this tile
    #pragma unroll 1
    for (int p = tid; p < 512; p += 256) {
        int qi = p >> 4;
        int si = p & 15;
        int sp = spb + si;
        if (sp >= SPN) continue;
        int q = qb + qi;

        float na[8], nb[8];
        #pragma unroll
        for (int i = 0; i < 8; i++) na[i] = g_tfn[q * 8 + i];
        #pragma unroll
        for (int j = 0; j < 8; j++) nb[j] = g_sfn[sp * 8 + j];

        float d[8][8];
        #pragma unroll
        for (int i = 0; i < 8; i++) {
            const float4* rp = reinterpret_cast<const float4*>(
                &ds[(qi * 8 + i) * EPI_PITCH + si * 8]);
            float4 v0 = rp[0];
            float4 v1 = rp[1];
            float dv[8] = {v0.x, v0.y, v0.z, v0.w, v1.x, v1.y, v1.z, v1.w};
            #pragma unroll
            for (int j = 0; j < 8; j++) {
                float den = fmaf(na[i], nb[j], 0.01f);
                d[i][j] = 1.0f - (dv[j] * INV256) * __frcp_rn(den);
            }
        }

        float r = otam_dp<false>(d) + otam_dp<true>(d);
        int c = labels[sp];
        atomicAdd(&out[q * NCLS + c], -r * g_invcnt[c]);
    }
}

// -------- launcher --------
extern "C" void kernel_launch(void* const* d_in, const int* in_sizes, int n_in,
                              void* d_out, int out_size) {
    const float* tf = (const float*)d_in[0];      // [2048, 8, 2048]
    const float* sf = (const float*)d_in[1];      // [100, 8, 2048]
    const int* labels = (const int*)d_in[2];      // [100]
    float* out = (float*)d_out;                   // [1, 2048, 20]

    cudaFuncSetAttribute(k_gemm, cudaFuncAttributeMaxDynamicSharedMemorySize, SM_BYTES);

    k_zero<<<(out_size + 255) / 256, 256>>>(out, out_size, labels);
    k_conv<<<(MROWS + NPAD) / 4, 256>>>(tf, sf);
    dim3 ggrid(NPAD / BN, MROWS / BM);
    k_gemm<<<ggrid, 256, SM_BYTES>>>(labels, out);
}

// round 8
// speedup vs baseline: 1.1008x; 1.1008x over previous
#include <cuda_runtime.h>
#include <cuda_bf16.h>
#include <cstdint>

// Problem dims
#define QN 2048
#define SN 8
#define DN 2048
#define SPN 100
#define NCLS 20
#define MROWS (QN * SN)          // 16384
#define NCOLS (SPN * SN)         // 800
#define NPAD 896                 // 7 * 128
#define LBDA 0.1f
#define ILBDA 10.0f
#define FP8SCALE 16.0f
#define INV256 0.00390625f

// GEMM tiling: CTA 128x128 x K128(fp8), SW128 smem, 3-stage cp.async, 2 CTA/SM
#define BM 128
#define BN 128
#define BK 128
#define NST 3
#define A_STG_B (BM * 128)       // 16384
#define B_STG_B (BN * 128)       // 16384
#define STG_B (A_STG_B + B_STG_B)
#define EPI_PITCH 132
#define SM_BYTES (NST * STG_B)   // 98304 (>= 128*132*4 = 67584)

// -------- scratch (device globals; allocation-free kernel_launch) --------
__device__ uint8_t g_A[(size_t)MROWS * DN];   // 32 MB (e4m3)
__device__ uint8_t g_B[(size_t)NPAD * DN];    // 1.8 MB (e4m3)
__device__ float g_tfn[MROWS];
__device__ float g_sfn[NPAD];
__device__ float g_invcnt[NCLS];

// -------- PTX helpers (compute_103-safe) --------
__device__ __forceinline__ void cpa16(uint32_t saddr, const void* g) {
    asm volatile("cp.async.cg.shared.global [%0], [%1], 16;"
                 :: "r"(saddr), "l"(__cvta_generic_to_global(g)) : "memory");
}
__device__ __forceinline__ void cpa_commit() {
    asm volatile("cp.async.commit_group;" ::: "memory");
}
__device__ __forceinline__ void cpa_wait1() {
    asm volatile("cp.async.wait_group 1;" ::: "memory");
}
__device__ __forceinline__ uint32_t smem_u32(const void* p) {
    uint32_t a;
    asm("{ .reg .u64 t; cvta.to.shared.u64 t, %1; cvt.u32.u64 %0, t; }"
        : "=r"(a) : "l"(p));
    return a;
}
#define LDSM4(r0, r1, r2, r3, addr)                                         \
    asm volatile("ldmatrix.sync.aligned.m8n8.x4.shared.b16 {%0,%1,%2,%3}, [%4];" \
                 : "=r"(r0), "=r"(r1), "=r"(r2), "=r"(r3) : "r"(addr))

__device__ __forceinline__ void mma_fp8(float* d, const uint32_t* a,
                                        uint32_t b0, uint32_t b1) {
    asm volatile(
        "mma.sync.aligned.m16n8k32.row.col.f32.e4m3.e4m3.f32 "
        "{%0,%1,%2,%3}, {%4,%5,%6,%7}, {%8,%9}, {%0,%1,%2,%3};"
        : "+f"(d[0]), "+f"(d[1]), "+f"(d[2]), "+f"(d[3])
        : "r"(a[0]), "r"(a[1]), "r"(a[2]), "r"(a[3]), "r"(b0), "r"(b1));
}
__device__ __forceinline__ uint16_t f2e4m3x2(float e0, float e1) {
    uint16_t r;
    asm("cvt.rn.satfinite.e4m3x2.f32 %0, %1, %2;" : "=h"(r) : "f"(e1), "f"(e0));
    return r;
}

// -------- kernel 0: zero output + class inverse counts --------
__global__ void k_zero(float* __restrict__ out, int n,
                       const int* __restrict__ labels) {
    int i = blockIdx.x * blockDim.x + threadIdx.x;
    if (i < n) out[i] = 0.0f;
    if (blockIdx.x == 0) {
        __shared__ int cnt[NCLS];
        if (threadIdx.x < NCLS) cnt[threadIdx.x] = 0;
        __syncthreads();
        if (threadIdx.x < SPN) atomicAdd(&cnt[labels[threadIdx.x]], 1);
        __syncthreads();
        if (threadIdx.x < NCLS) {
            int c = cnt[threadIdx.x];
            g_invcnt[threadIdx.x] = 1.0f / (float)(c > 0 ? c : 1);
        }
    }
}

// -------- kernel 1: fp32 -> e4m3 (x16) + fp32 row norms. 4 rows/block ----
__global__ void __launch_bounds__(256) k_conv(const float* __restrict__ tf,
                                              const float* __restrict__ sf) {
    const int rg = threadIdx.x >> 6;
    const int t = threadIdx.x & 63;
    int row = blockIdx.x * 4 + rg;

    const float* src;
    uint8_t* dst;
    float* norms;
    bool pad = false;
    if (row < MROWS) {
        src = tf + (size_t)row * DN;
        dst = g_A + (size_t)row * DN;
        norms = &g_tfn[row];
    } else {
        int r = row - MROWS;
        pad = (r >= NCOLS);
        src = sf + (size_t)r * DN;
        dst = g_B + (size_t)r * DN;
        norms = &g_sfn[r];
    }

    float ss = 0.0f;
    uint32_t ov[8];
    #pragma unroll
    for (int j = 0; j < 8; j++) ov[j] = 0u;
    if (!pad) {
        const float4* s = reinterpret_cast<const float4*>(src);
        float4 v[8];
        #pragma unroll
        for (int j = 0; j < 8; j++) v[j] = s[t + 64 * j];
        #pragma unroll
        for (int j = 0; j < 8; j++) {
            ss = fmaf(v[j].x, v[j].x, fmaf(v[j].y, v[j].y,
                 fmaf(v[j].z, v[j].z, fmaf(v[j].w, v[j].w, ss))));
            uint16_t lo = f2e4m3x2(v[j].x * FP8SCALE, v[j].y * FP8SCALE);
            uint16_t hi = f2e4m3x2(v[j].z * FP8SCALE, v[j].w * FP8SCALE);
            ov[j] = (uint32_t)lo | ((uint32_t)hi << 16);
        }
    }
    uint2* drow = reinterpret_cast<uint2*>(dst);
    #pragma unroll
    for (int j = 0; j < 4; j++)
        drow[t * 4 + j] = make_uint2(ov[2 * j], ov[2 * j + 1]);

    #pragma unroll
    for (int o = 16; o; o >>= 1) ss += __shfl_xor_sync(0xFFFFFFFFu, ss, o);
    __shared__ float ws[8];
    if ((threadIdx.x & 31) == 0) ws[threadIdx.x >> 5] = ss;
    __syncthreads();
    if (t == 0 && !pad)
        *norms = sqrtf(ws[rg * 2] + ws[rg * 2 + 1]);
}

// -------- OTAM soft-DTW (reads distances from smem on the fly) --------
__device__ __forceinline__ float softmin2(float a, float b) {
    float mn = fminf(a, b);
    float df = fabsf(a - b);
    return mn - LBDA * __logf(1.0f + __expf(-df * ILBDA));
}
__device__ __forceinline__ float softmin3(float a, float b, float c) {
    float mn = fminf(a, fminf(b, c));
    float s = __expf((mn - a) * ILBDA) + __expf((mn - b) * ILBDA) + __expf((mn - c) * ILBDA);
    return mn - LBDA * __logf(s);
}

template <bool TR>
__device__ __forceinline__ float otam_dp_smem(const float* __restrict__ b) {
    // element(i,j) of the 8x8 block
    auto D = [&](int i, int j) -> float {
        return TR ? b[j * EPI_PITCH + i] : b[i * EPI_PITCH + j];
    };
    float prev[10];
    prev[0] = 0.0f;
    #pragma unroll
    for (int m = 1; m <= 8; m++) prev[m] = prev[m - 1] + D(0, m - 1);
    prev[9] = prev[8];
    #pragma unroll
    for (int i = 1; i < 8; i++) {
        float cur[10];
        cur[0] = 0.0f;
        cur[1] = D(i, 0) + softmin3(prev[0], prev[1], 0.0f);
        #pragma unroll
        for (int m = 2; m <= 8; m++)
            cur[m] = D(i, m - 1) + softmin2(prev[m - 1], cur[m - 1]);
        cur[9] = softmin3(prev[8], prev[9], cur[8]);
        #pragma unroll
        for (int m = 0; m < 10; m++) prev[m] = cur[m];
    }
    return prev[9];
}

// -------- kernel 2: fp8 GEMM + fused normalized-distance epilogue + DP ----
__global__ void __launch_bounds__(256, 2) k_gemm(const int* __restrict__ labels,
                                                 float* __restrict__ out) {
    extern __shared__ __align__(128) char smem_raw[];
    uint32_t sb = smem_u32(smem_raw);

    const int tid = threadIdx.x;
    const int lane = tid & 31;
    const int warp = tid >> 5;
    const int wm = warp >> 2;     // 0..1
    const int wn = warp & 3;      // 0..3
    const int bm = blockIdx.y * BM;
    const int bn = blockIdx.x * BN;

    // loader: 16B chunks; thread -> (row tid>>3, chunk tid&7), rows += 32
    const int lrow = tid >> 3;
    const int lcc = tid & 7;
    const uint32_t s_off =
        (uint32_t)(lrow * 128 + ((lcc ^ (lrow & 7)) << 4));
    const uint8_t* gA = g_A + (size_t)(bm + lrow) * DN + lcc * 16;
    const uint8_t* gB = g_B + (size_t)(bn + lrow) * DN + lcc * 16;

    float acc[4][4][4];
    #pragma unroll
    for (int i = 0; i < 4; i++)
        #pragma unroll
        for (int j = 0; j < 4; j++)
            #pragma unroll
            for (int k = 0; k < 4; k++) acc[i][j][k] = 0.0f;

    const int NSTG = DN / BK;  // 16

    auto load_stage = [&](int st, int k0) {
        uint32_t base = sb + (uint32_t)(st * STG_B);
        #pragma unroll
        for (int i = 0; i < 4; i++)
            cpa16(base + s_off + (uint32_t)(i * 32 * 128),
                  gA + k0 + (size_t)i * 32 * DN);
        #pragma unroll
        for (int i = 0; i < 4; i++)
            cpa16(base + A_STG_B + s_off + (uint32_t)(i * 32 * 128),
                  gB + k0 + (size_t)i * 32 * DN);
        cpa_commit();
    };

    load_stage(0, 0);
    load_stage(1, BK);

    const uint32_t hl = (uint32_t)(lane >> 4);
    const uint32_t l7 = (uint32_t)(lane & 7);
    const uint32_t aRow = (uint32_t)((wm * 64 + (lane & 15)) * 128);
    const uint32_t bRow = (uint32_t)(A_STG_B + (wn * 32 + (lane & 15)) * 128);

    #pragma unroll 1
    for (int s = 0; s < NSTG; s++) {
        cpa_wait1();
        __syncthreads();
        if (s + 2 < NSTG) load_stage((s + 2) % NST, (s + 2) * BK);
        else cpa_commit();

        uint32_t stb = sb + (uint32_t)((s % NST) * STG_B);

        #pragma unroll
        for (int kk = 0; kk < 4; kk++) {
            uint32_t xc = (((uint32_t)(2 * kk) + hl) ^ l7) << 4;
            uint32_t a[4][4];
            #pragma unroll
            for (int i = 0; i < 4; i++)
                LDSM4(a[i][0], a[i][1], a[i][2], a[i][3],
                      stb + aRow + (uint32_t)(i * 16 * 128) + xc);
            uint32_t b[2][4];
            #pragma unroll
            for (int jj = 0; jj < 2; jj++)
                LDSM4(b[jj][0], b[jj][1], b[jj][2], b[jj][3],
                      stb + bRow + (uint32_t)(jj * 16 * 128) + xc);
            #pragma unroll
            for (int i = 0; i < 4; i++)
                #pragma unroll
                for (int jj = 0; jj < 2; jj++) {
                    mma_fp8(acc[i][2 * jj],     a[i], b[jj][0], b[jj][2]);
                    mma_fp8(acc[i][2 * jj + 1], a[i], b[jj][1], b[jj][3]);
                }
        }
    }

    // ---- epilogue: normalize acc -> smem distance tile ----
    __syncthreads();
    float* ds = reinterpret_cast<float*>(smem_raw);
    {
        const int r0l = wm * 64 + (lane >> 2);
        const int c0l = wn * 32 + (lane & 3) * 2;
        float rn[8], cn[8];
        #pragma unroll
        for (int i = 0; i < 4; i++) {
            rn[2 * i]     = g_tfn[bm + r0l + i * 16];
            rn[2 * i + 1] = g_tfn[bm + r0l + i * 16 + 8];
        }
        #pragma unroll
        for (int j = 0; j < 4; j++) {
            int c = bn + c0l + j * 8;
            cn[2 * j]     = (c < NCOLS)     ? g_sfn[c]     : 1.0f;
            cn[2 * j + 1] = (c + 1 < NCOLS) ? g_sfn[c + 1] : 1.0f;
        }
        #pragma unroll
        for (int i = 0; i < 4; i++) {
            #pragma unroll
            for (int j = 0; j < 4; j++) {
                int r = r0l + i * 16;
                int c = c0l + j * 8;
                float d00 = 1.0f - (acc[i][j][0] * INV256) *
                            __frcp_rn(fmaf(rn[2 * i], cn[2 * j], 0.01f));
                float d01 = 1.0f - (acc[i][j][1] * INV256) *
                            __frcp_rn(fmaf(rn[2 * i], cn[2 * j + 1], 0.01f));
                float d10 = 1.0f - (acc[i][j][2] * INV256) *
                            __frcp_rn(fmaf(rn[2 * i + 1], cn[2 * j], 0.01f));
                float d11 = 1.0f - (acc[i][j][3] * INV256) *
                            __frcp_rn(fmaf(rn[2 * i + 1], cn[2 * j + 1], 0.01f));
                *reinterpret_cast<float2*>(&ds[r * EPI_PITCH + c]) =
                    make_float2(d00, d01);
                *reinterpret_cast<float2*>(&ds[(r + 8) * EPI_PITCH + c]) =
                    make_float2(d10, d11);
            }
        }
    }
    __syncthreads();

    // ---- per-pair OTAM DP: exactly 1 pair per thread ----
    {
        const int qi = tid >> 4;          // 0..15
        const int si = tid & 15;          // 0..15
        const int sp = (bn >> 3) + si;
        if (sp < SPN) {
            const int q = (bm >> 3) + qi;
            const float* base = ds + (qi * 8) * EPI_PITCH + si * 8;
            float r = otam_dp_smem<false>(base) + otam_dp_smem<true>(base);
            int c = labels[sp];
            atomicAdd(&out[q * NCLS + c], -r * g_invcnt[c]);
        }
    }
}

// -------- launcher --------
extern "C" void kernel_launch(void* const* d_in, const int* in_sizes, int n_in,
                              void* d_out, int out_size) {
    const float* tf = (const float*)d_in[0];      // [2048, 8, 2048]
    const float* sf = (const float*)d_in[1];      // [100, 8, 2048]
    const int* labels = (const int*)d_in[2];      // [100]
    float* out = (float*)d_out;                   // [1, 2048, 20]

    cudaFuncSetAttribute(k_gemm, cudaFuncAttributeMaxDynamicSharedMemorySize, SM_BYTES);

    k_zero<<<(out_size + 255) / 256, 256>>>(out, out_size, labels);
    k_conv<<<(MROWS + NPAD) / 4, 256>>>(tf, sf);
    dim3 ggrid(NPAD / BN, MROWS / BM);
    k_gemm<<<ggrid, 256, SM_BYTES>>>(labels, out);
}